// round 11
// baseline (speedup 1.0000x reference)
#include <cuda_runtime.h>
#include <cuda_fp16.h>
#include <cstdint>
#include <cstddef>

// Problem constants
#define BATCH 32
#define NREG  36
#define DIM   2048
#define RANK  512
#define KTOT  1024              // 2*RANK (feat || coord)
#define BN    (BATCH * NREG)    // 1152
#define NPAIR (BN * NREG)       // 41472 pair rows

// Main kernel tiling (4 CTAs/SM)
#define DTILE 64                // d columns per CTA
#define NCOL  144               // 4 i x 36 j pair-columns per CTA
#define KC    64                // k (halves) per chunk = 128 B per row
#define NTHR  128

// Scratch
__device__ float g_G[BN * KTOT];
__device__ float g_H[BN * KTOT];
__device__ __half g_PTh[(size_t)DIM * KTOT];      // P^T as fp16: PT[d][r]
__device__ __half g_Zh[(size_t)NPAIR * KTOT];     // Z[pair][r] as fp16 (~85 MB)

// ---------------------------------------------------------------------------
__device__ __forceinline__ uint32_t smem_u32(const void* p) {
    uint32_t a;
    asm("{ .reg .u64 t; cvta.to.shared.u64 t, %1; cvt.u32.u64 %0, t; }" : "=r"(a) : "l"(p));
    return a;
}

// fp16 MMA: D(16x8,f32) += A(16x16,f16) * B(16x8,f16)
__device__ __forceinline__ void mma_f16(float c[4], const uint32_t a[4], const uint32_t b[2]) {
    asm volatile(
        "mma.sync.aligned.m16n8k16.row.col.f32.f16.f16.f32 "
        "{%0,%1,%2,%3}, {%4,%5,%6,%7}, {%8,%9}, {%0,%1,%2,%3};\n"
        : "+f"(c[0]), "+f"(c[1]), "+f"(c[2]), "+f"(c[3])
        : "r"(a[0]), "r"(a[1]), "r"(a[2]), "r"(a[3]), "r"(b[0]), "r"(b[1]));
}

__device__ __forceinline__ void ldsm_x4(uint32_t& r0, uint32_t& r1, uint32_t& r2, uint32_t& r3,
                                        uint32_t addr) {
    asm volatile("ldmatrix.sync.aligned.m8n8.x4.shared.b16 {%0,%1,%2,%3}, [%4];"
                 : "=r"(r0), "=r"(r1), "=r"(r2), "=r"(r3) : "r"(addr));
}
__device__ __forceinline__ void ldsm_x2(uint32_t& r0, uint32_t& r1, uint32_t addr) {
    asm volatile("ldmatrix.sync.aligned.m8n8.x2.shared.b16 {%0,%1}, [%2];"
                 : "=r"(r0), "=r"(r1) : "r"(addr));
}

__device__ __forceinline__ void cp16(uint32_t dst, const void* src) {
    asm volatile("cp.async.cg.shared.global [%0], [%1], 16;" :: "r"(dst), "l"(src) : "memory");
}
#define CP_COMMIT() asm volatile("cp.async.commit_group;" ::: "memory")
#define CP_WAIT0()  asm volatile("cp.async.wait_group 0;" ::: "memory")

__device__ __forceinline__ uint32_t packh2(float lo, float hi) {
    __half2 h = __floats2half2_rn(lo, hi);
    return *(uint32_t*)&h;
}

// ---------------------------------------------------------------------------
// prep: fused stage1 (blocks 0..143) + transpose_P / coord (blocks 144..4495).
//   stage1: C[1152,1024] = mm @ [Uf|Vf], fp16 MMA, CTA tile 128m x 64n
//           -> 144 CTAs = full chip wave (was 72 = half-idle).
//   prelude blocks backfill as stage1 drains.
// ---------------------------------------------------------------------------
__global__ __launch_bounds__(256)
void prep(const float* __restrict__ mm,
          const float* __restrict__ Uf, const float* __restrict__ Vf,
          const float* __restrict__ Pf, const float* __restrict__ Pc,
          const float* __restrict__ coords,
          const float* __restrict__ Uc, const float* __restrict__ Vc) {
    __shared__ uint32_t As[128][20];   // stage1 A: [m][kpair], 16 used + 4 pad
    __shared__ uint32_t Bs[16][72];    // stage1 B: [kpair][n], 64 used + 8 pad
    __shared__ float    t[32][33];     // transpose tile

    const int tid = threadIdx.x;

    if (blockIdx.x >= 144) {
        int bx2 = blockIdx.x - 144;
        if (bx2 < 2048) {
            // ---- transpose P = [Pf ; Pc] -> PTh fp16 ----
            int r0 = (bx2 & 31) * 32;
            int d0 = (bx2 >> 5) * 32;
            int tx = tid & 31, ty = tid >> 5;     // 32 x 8
#pragma unroll
            for (int q = 0; q < 4; q++) {
                int r = r0 + ty + q * 8;
                const float* src = (r < RANK) ? (Pf + (size_t)r * DIM)
                                              : (Pc + (size_t)(r - RANK) * DIM);
                t[ty + q * 8][tx] = src[d0 + tx];
            }
            __syncthreads();
#pragma unroll
            for (int q = 0; q < 4; q++) {
                int d = d0 + ty + q * 8;
                g_PTh[(size_t)d * KTOT + r0 + tx] = __float2half_rn(t[tx][ty + q * 8]);
            }
        } else {
            // ---- coord projections (K=4) ----
            int idx = (bx2 - 2048) * 256 + tid;   // [0, BN*RANK)
            int row = idx >> 9;
            int n   = idx & 511;
            const float* c = coords + row * 4;
            float c0 = c[0], c1 = c[1], c2 = c[2], c3 = c[3];
            g_G[(size_t)row * KTOT + RANK + n] =
                c0 * Uc[n] + c1 * Uc[512 + n] + c2 * Uc[1024 + n] + c3 * Uc[1536 + n];
            g_H[(size_t)row * KTOT + RANK + n] =
                c0 * Vc[n] + c1 * Vc[512 + n] + c2 * Vc[1024 + n] + c3 * Vc[1536 + n];
        }
        return;
    }

    // ---- stage1: CTA tile 128m x 64n ----
    const int lane = tid & 31, wid = tid >> 5;
    const int warpM = wid & 3, warpN = wid >> 2;
    const int mblk = (blockIdx.x >> 4) * 128;   // 9 m-tiles
    const int nblk = (blockIdx.x & 15) * 64;    // 16 n-tiles

    const float* W = (nblk < 512) ? (Uf + nblk) : (Vf + (nblk - 512));

    float acc[2][4][4];
#pragma unroll
    for (int mt = 0; mt < 2; mt++)
#pragma unroll
        for (int nt = 0; nt < 4; nt++)
#pragma unroll
            for (int q = 0; q < 4; q++) acc[mt][nt][q] = 0.f;

    for (int kc = 0; kc < DIM; kc += 32) {
        // A tile: 128 rows x 32 k floats -> 16 packed uints per row.
#pragma unroll
        for (int p = 0; p < 4; p++) {
            int m  = (tid >> 3) + 32 * p;
            int k4 = (tid & 7) * 4;
            float4 v = *(const float4*)(mm + (size_t)(mblk + m) * DIM + kc + k4);
            uint2 tt;
            tt.x = packh2(v.x, v.y);
            tt.y = packh2(v.z, v.w);
            *(uint2*)&As[m][(tid & 7) * 2] = tt;
        }
        // B tile: 16 kpairs x 64 n, one uint4 per thread.
        {
            int kp = tid >> 4;             // 0..15
            int n4 = (tid & 15) * 4;       // 0..60
            const float* w0 = W + (size_t)(kc + 2 * kp) * 512 + n4;
            float4 v0 = *(const float4*)w0;
            float4 v1 = *(const float4*)(w0 + 512);
            uint4 tt;
            tt.x = packh2(v0.x, v1.x);
            tt.y = packh2(v0.y, v1.y);
            tt.z = packh2(v0.z, v1.z);
            tt.w = packh2(v0.w, v1.w);
            *(uint4*)&Bs[kp][n4] = tt;
        }
        __syncthreads();

#pragma unroll
        for (int kk = 0; kk < 2; kk++) {
            uint32_t a[2][4];
#pragma unroll
            for (int mt = 0; mt < 2; mt++) {
                int mb = warpM * 32 + mt * 16;
                int r = lane >> 2, kq = kk * 8 + (lane & 3);
                a[mt][0] = As[mb + r][kq];
                a[mt][1] = As[mb + r + 8][kq];
                a[mt][2] = As[mb + r][kq + 4];
                a[mt][3] = As[mb + r + 8][kq + 4];
            }
#pragma unroll
            for (int nt = 0; nt < 4; nt++) {
                int nb = warpN * 32 + nt * 8;
                uint32_t b[2];
                b[0] = Bs[kk * 8 + (lane & 3)][nb + (lane >> 2)];
                b[1] = Bs[kk * 8 + (lane & 3) + 4][nb + (lane >> 2)];
                mma_f16(acc[0][nt], a[0], b);
                mma_f16(acc[1][nt], a[1], b);
            }
        }
        __syncthreads();
    }

    float* Cout = (nblk < 512) ? g_G : g_H;
    const int colbase = (nblk < 512) ? nblk : (nblk - 512);
#pragma unroll
    for (int mt = 0; mt < 2; mt++)
#pragma unroll
        for (int nt = 0; nt < 4; nt++)
#pragma unroll
            for (int rh = 0; rh < 2; rh++)
#pragma unroll
                for (int e = 0; e < 2; e++) {
                    int row = mblk + warpM * 32 + mt * 16 + (lane >> 2) + rh * 8;
                    int col = colbase + warpN * 32 + nt * 8 + (lane & 3) * 2 + e;
                    Cout[(size_t)row * KTOT + col] = acc[mt][nt][rh * 2 + e];
                }
}

// ---------------------------------------------------------------------------
// Z precompute: g_Zh[pair][r] = fp16(relu(G[gi][r] * H[b*36+j][r]))
// ---------------------------------------------------------------------------
__global__ __launch_bounds__(256)
void zbuild() {
    const int gi = blockIdx.x;            // 0..1151
    const int b  = gi / 36;
    const int t  = threadIdx.x;           // 0..255, KTOT/4 = 256

    float4 g = ((const float4*)(g_G + (size_t)gi * KTOT))[t];
    const float4* Hb = (const float4*)(g_H + (size_t)b * 36 * KTOT);
    uint2* Zb = (uint2*)(g_Zh + (size_t)gi * 36 * KTOT);

#pragma unroll 4
    for (int j = 0; j < 36; j++) {
        float4 h = Hb[j * (KTOT / 4) + t];
        uint2 z;
        z.x = packh2(fmaxf(g.x * h.x, 0.f), fmaxf(g.y * h.y, 0.f));
        z.y = packh2(fmaxf(g.z * h.z, 0.f), fmaxf(g.w * h.w, 0.f));
        Zb[j * (KTOT / 4) + t] = z;
    }
}

// ---------------------------------------------------------------------------
// Main kernel: pipelined fp16 GEMM, 4 CTAs/SM, XOR-swizzled smem,
//   hoisted cp.async addressing. One barrier per chunk. (Unchanged from R10.)
// ---------------------------------------------------------------------------
#define ASZ   (DTILE * 128)          // 8192 B per A buffer
#define ZSZ   (NCOL * 128)           // 18432 B per Z buffer
#define OFF_A   0
#define OFF_Z   (2 * ASZ)            // 16384
#define SMEM_MAIN (OFF_Z + 2 * ZSZ)  // 53248

__global__ __launch_bounds__(NTHR, 4)
void pairwise_mm(const float* __restrict__ mm, float* __restrict__ out) {
    extern __shared__ char smem[];
    const uint32_t sbase = smem_u32(smem);

    const int tid = threadIdx.x;
    const int lane = tid & 31, wid = tid >> 5;
    const int warpM = wid & 1, warpN = wid >> 1;
    const int d0 = blockIdx.x * DTILE;
    const int i0 = blockIdx.y * 4;                      // 4 global i rows
    const size_t zrow0 = (size_t)blockIdx.y * NCOL;     // first pair row

    // ---- hoisted cp.async addressing ----
    const int r8 = tid >> 3;                 // 0..15
    const int kq = tid & 7;
    const uint32_t cpdst = r8 * 128 + ((kq ^ (r8 & 7)) << 4);
    const __half* srcA = g_PTh + (size_t)(d0 + r8) * KTOT + kq * 8;
    const __half* srcZ = g_Zh + (zrow0 + r8) * KTOT + kq * 8;

    // ---- issue chunk 0 (A + Z) ----
    {
#pragma unroll
        for (int q = 0; q < 4; q++)
            cp16(sbase + OFF_A + cpdst + q * 2048, srcA + (size_t)q * 16 * KTOT);
#pragma unroll
        for (int p = 0; p < 9; p++)
            cp16(sbase + OFF_Z + cpdst + p * 2048, srcZ + (size_t)p * 16 * KTOT);
        CP_COMMIT();
    }

    // ---- per-thread ldmatrix row bases (bytes) and swizzle params ----
    const int sx = lane & 7;
    const int aRow  = (warpM * 32 + (lane & 15)) * 128;
    const int kbitA = lane >> 4;
    const int bRow  = (warpN * 72 + (lane & 7) + ((lane >> 4) << 3)) * 128;
    const int kbitB = (lane >> 3) & 1;
    const int l2 = lane & 15;
    const int b2Row  = (warpN * 72 + 64 + (l2 & 7)) * 128;
    const int kbitB2 = l2 >> 3;

    float acc[2][9][4];
#pragma unroll
    for (int mt = 0; mt < 2; mt++)
#pragma unroll
        for (int nt = 0; nt < 9; nt++)
#pragma unroll
            for (int q = 0; q < 4; q++) acc[mt][nt][q] = 0.f;

    for (int c = 0; c < KTOT / KC; c++) {        // 16 chunks of 64 halves
        const int buf = c & 1;
        const uint32_t Zb = sbase + OFF_Z + buf * ZSZ;
        const uint32_t Ab = sbase + OFF_A + buf * ASZ;

        // ---- single rendezvous: chunk-c data resident, other buffer free ----
        CP_WAIT0();
        __syncthreads();

        // ---- issue chunk c+1 into the freed buffer (covers under MMA) ----
        if (c < KTOT / KC - 1) {
            const uint32_t An = sbase + OFF_A + (buf ^ 1) * ASZ;
            const uint32_t Zn = sbase + OFF_Z + (buf ^ 1) * ZSZ;
            const __half* sA = srcA + (size_t)(c + 1) * KC;
            const __half* sZ = srcZ + (size_t)(c + 1) * KC;
#pragma unroll
            for (int q = 0; q < 4; q++)
                cp16(An + cpdst + q * 2048, sA + (size_t)q * 16 * KTOT);
#pragma unroll
            for (int p = 0; p < 9; p++)
                cp16(Zn + cpdst + p * 2048, sZ + (size_t)p * 16 * KTOT);
            CP_COMMIT();
        }

        // ---- fragments + MMA: 4 k16-steps per chunk ----
#pragma unroll
        for (int kk = 0; kk < 4; kk++) {
            const int kk2 = kk * 2;
            const int swA  = (((kk2 + kbitA)  ^ sx) << 4);
            const int swB  = (((kk2 + kbitB)  ^ sx) << 4);
            const int swB2 = (((kk2 + kbitB2) ^ sx) << 4);

            uint32_t a[2][4];
#pragma unroll
            for (int mt = 0; mt < 2; mt++) {
                uint32_t addr = Ab + aRow + mt * (16 * 128) + swA;
                ldsm_x4(a[mt][0], a[mt][1], a[mt][2], a[mt][3], addr);
            }
            uint32_t b[9][2];
#pragma unroll
            for (int p = 0; p < 4; p++) {
                uint32_t addr = Zb + bRow + p * (16 * 128) + swB;
                ldsm_x4(b[p * 2][0], b[p * 2][1], b[p * 2 + 1][0], b[p * 2 + 1][1], addr);
            }
            {
                uint32_t addr = Zb + b2Row + swB2;
                ldsm_x2(b[8][0], b[8][1], addr);
            }
#pragma unroll
            for (int nt = 0; nt < 9; nt++) {
                mma_f16(acc[0][nt], a[0], b[nt]);
                mma_f16(acc[1][nt], a[1], b[nt]);
            }
        }
    }

    // ---- Epilogue: max over j within each 36-group, + residual ----
    const int s = lane & 3;
    float gmax[2][2][2];   // [mt][rowhalf][group]
#pragma unroll
    for (int mt = 0; mt < 2; mt++)
#pragma unroll
        for (int rh = 0; rh < 2; rh++)
#pragma unroll
            for (int g2 = 0; g2 < 2; g2++) gmax[mt][rh][g2] = -1e30f;

#pragma unroll
    for (int nt = 0; nt < 9; nt++) {
#pragma unroll
        for (int e = 0; e < 2; e++) {
            int nloc = nt * 8 + s * 2 + e;      // 0..71
            int g2 = (nloc >= 36) ? 1 : 0;
#pragma unroll
            for (int mt = 0; mt < 2; mt++)
#pragma unroll
                for (int rh = 0; rh < 2; rh++) {
                    float v = acc[mt][nt][rh * 2 + e];
                    gmax[mt][rh][g2] = fmaxf(gmax[mt][rh][g2], v);
                }
        }
    }
#pragma unroll
    for (int mt = 0; mt < 2; mt++)
#pragma unroll
        for (int rh = 0; rh < 2; rh++)
#pragma unroll
            for (int g2 = 0; g2 < 2; g2++) {
                float v = gmax[mt][rh][g2];
                v = fmaxf(v, __shfl_xor_sync(0xffffffffu, v, 1));
                v = fmaxf(v, __shfl_xor_sync(0xffffffffu, v, 2));
                gmax[mt][rh][g2] = v;
            }

    if (s < 2) {
        int iglob = i0 + warpN * 2 + s;
        size_t rowbase = (size_t)iglob * DIM;
#pragma unroll
        for (int mt = 0; mt < 2; mt++)
#pragma unroll
            for (int rh = 0; rh < 2; rh++) {
                int d = d0 + warpM * 32 + mt * 16 + (lane >> 2) + rh * 8;
                out[rowbase + d] = gmax[mt][rh][s] + mm[rowbase + d];
            }
    }
}

// ---------------------------------------------------------------------------
extern "C" void kernel_launch(void* const* d_in, const int* in_sizes, int n_in,
                              void* d_out, int out_size) {
    const float* mm     = (const float*)d_in[0];
    const float* coords = (const float*)d_in[1];
    const float* Uf     = (const float*)d_in[2];
    const float* Vf     = (const float*)d_in[3];
    const float* Pf     = (const float*)d_in[4];
    const float* Uc     = (const float*)d_in[5];
    const float* Vc     = (const float*)d_in[6];
    const float* Pc     = (const float*)d_in[7];
    float* out = (float*)d_out;

    cudaFuncSetAttribute(pairwise_mm,
                         cudaFuncAttributeMaxDynamicSharedMemorySize, SMEM_MAIN);

    prep<<<4496, 256>>>(mm, Uf, Vf, Pf, Pc, coords, Uc, Vc);   // launch 0

    zbuild<<<BN, 256>>>();                                     // launch 1

    dim3 g2(DIM / DTILE, BN / 4);   // 32 x 288
    pairwise_mm<<<g2, NTHR, SMEM_MAIN>>>(mm, out);             // launch 2
}

// round 12
// speedup vs baseline: 1.1178x; 1.1178x over previous
#include <cuda_runtime.h>
#include <cuda_fp16.h>
#include <cstdint>
#include <cstddef>

// Problem constants
#define BATCH 32
#define NREG  36
#define DIM   2048
#define RANK  512
#define KTOT  1024              // 2*RANK (feat || coord)
#define BN    (BATCH * NREG)    // 1152
#define NPAIR (BN * NREG)       // 41472 pair rows

// Main kernel tiling (4 CTAs/SM)
#define DTILE 64                // d columns per CTA
#define NCOL  144               // 4 i x 36 j pair-columns per CTA
#define KC    64                // k (halves) per chunk = 128 B per row
#define NTHR  128

// Scratch
__device__ float g_G[BN * KTOT];
__device__ float g_H[BN * KTOT];
__device__ float g_S[2 * BN * KTOT];              // split-K partials (9.4 MB)
__device__ __half g_PTh[(size_t)DIM * KTOT];      // P^T as fp16: PT[d][r]
__device__ __half g_Zh[(size_t)NPAIR * KTOT];     // Z[pair][r] as fp16 (~85 MB)

// ---------------------------------------------------------------------------
__device__ __forceinline__ uint32_t smem_u32(const void* p) {
    uint32_t a;
    asm("{ .reg .u64 t; cvta.to.shared.u64 t, %1; cvt.u32.u64 %0, t; }" : "=r"(a) : "l"(p));
    return a;
}

// fp16 MMA: D(16x8,f32) += A(16x16,f16) * B(16x8,f16)
__device__ __forceinline__ void mma_f16(float c[4], const uint32_t a[4], const uint32_t b[2]) {
    asm volatile(
        "mma.sync.aligned.m16n8k16.row.col.f32.f16.f16.f32 "
        "{%0,%1,%2,%3}, {%4,%5,%6,%7}, {%8,%9}, {%0,%1,%2,%3};\n"
        : "+f"(c[0]), "+f"(c[1]), "+f"(c[2]), "+f"(c[3])
        : "r"(a[0]), "r"(a[1]), "r"(a[2]), "r"(a[3]), "r"(b[0]), "r"(b[1]));
}

__device__ __forceinline__ void ldsm_x4(uint32_t& r0, uint32_t& r1, uint32_t& r2, uint32_t& r3,
                                        uint32_t addr) {
    asm volatile("ldmatrix.sync.aligned.m8n8.x4.shared.b16 {%0,%1,%2,%3}, [%4];"
                 : "=r"(r0), "=r"(r1), "=r"(r2), "=r"(r3) : "r"(addr));
}
__device__ __forceinline__ void ldsm_x2(uint32_t& r0, uint32_t& r1, uint32_t addr) {
    asm volatile("ldmatrix.sync.aligned.m8n8.x2.shared.b16 {%0,%1}, [%2];"
                 : "=r"(r0), "=r"(r1) : "r"(addr));
}

__device__ __forceinline__ void cp16(uint32_t dst, const void* src) {
    asm volatile("cp.async.cg.shared.global [%0], [%1], 16;" :: "r"(dst), "l"(src) : "memory");
}
#define CP_COMMIT() asm volatile("cp.async.commit_group;" ::: "memory")
#define CP_WAIT0()  asm volatile("cp.async.wait_group 0;" ::: "memory")

__device__ __forceinline__ uint32_t packh2(float lo, float hi) {
    __half2 h = __floats2half2_rn(lo, hi);
    return *(uint32_t*)&h;
}

// ---------------------------------------------------------------------------
// Prelude: fused transpose_P + coord projections. (R10 version, validated.)
// ---------------------------------------------------------------------------
__global__ __launch_bounds__(256)
void prelude(const float* __restrict__ Pf, const float* __restrict__ Pc,
             const float* __restrict__ coords,
             const float* __restrict__ Uc, const float* __restrict__ Vc) {
    __shared__ float t[32][33];
    const int tid = threadIdx.x;
    if (blockIdx.x < 2048) {
        int r0 = (blockIdx.x & 31) * 32;
        int d0 = (blockIdx.x >> 5) * 32;
        int tx = tid & 31, ty = tid >> 5;     // 32 x 8
#pragma unroll
        for (int q = 0; q < 4; q++) {
            int r = r0 + ty + q * 8;
            const float* src = (r < RANK) ? (Pf + (size_t)r * DIM)
                                          : (Pc + (size_t)(r - RANK) * DIM);
            t[ty + q * 8][tx] = src[d0 + tx];
        }
        __syncthreads();
#pragma unroll
        for (int q = 0; q < 4; q++) {
            int d = d0 + ty + q * 8;
            g_PTh[(size_t)d * KTOT + r0 + tx] = __float2half_rn(t[tx][ty + q * 8]);
        }
    } else {
        int idx = (blockIdx.x - 2048) * 256 + tid;   // [0, BN*RANK)
        int row = idx >> 9;
        int n   = idx & 511;
        const float* c = coords + row * 4;
        float c0 = c[0], c1 = c[1], c2 = c[2], c3 = c[3];
        g_G[(size_t)row * KTOT + RANK + n] =
            c0 * Uc[n] + c1 * Uc[512 + n] + c2 * Uc[1024 + n] + c3 * Uc[1536 + n];
        g_H[(size_t)row * KTOT + RANK + n] =
            c0 * Vc[n] + c1 * Vc[512 + n] + c2 * Vc[1024 + n] + c3 * Vc[1536 + n];
    }
}

// ---------------------------------------------------------------------------
// Stage 1 (fp16, split-K): partial[kz][1152,1024] = mm[:, kz*1024:(kz+1)*1024]
//   @ [Uf|Vf] rows. Same 128x128 tile / loop body as the validated R10
//   version (intensity preserved); grid z in {0,1} -> 144 CTAs fill the chip.
// ---------------------------------------------------------------------------
__global__ __launch_bounds__(256, 2)
void stage1_feat(const float* __restrict__ mm,
                 const float* __restrict__ Uf,
                 const float* __restrict__ Vf) {
    __shared__ uint32_t As[128][20];   // [m][kpair], 16 used + 4 pad
    __shared__ uint32_t Bs[16][136];   // [kpair][n], pad to 136

    const int tid = threadIdx.x;
    const int lane = tid & 31, wid = tid >> 5;
    const int warpM = wid & 3, warpN = wid >> 2;
    const int mblk = blockIdx.y * 128;
    const int nblk = blockIdx.x * 128;
    const int kz   = blockIdx.z;                  // 0 or 1
    const int kbeg = kz * (DIM / 2);
    const int kend = kbeg + (DIM / 2);

    const float* W = (nblk < 512) ? (Uf + nblk) : (Vf + (nblk - 512));

    float acc[2][8][4];
#pragma unroll
    for (int mt = 0; mt < 2; mt++)
#pragma unroll
        for (int nt = 0; nt < 8; nt++)
#pragma unroll
            for (int q = 0; q < 4; q++) acc[mt][nt][q] = 0.f;

    for (int kc = kbeg; kc < kend; kc += 32) {
        // A tile: 128 rows x 32 k floats -> 16 packed uints per row.
#pragma unroll
        for (int p = 0; p < 4; p++) {
            int m  = (tid >> 3) + 32 * p;
            int k4 = (tid & 7) * 4;
            float4 v = *(const float4*)(mm + (size_t)(mblk + m) * DIM + kc + k4);
            uint2 t;
            t.x = packh2(v.x, v.y);
            t.y = packh2(v.z, v.w);
            *(uint2*)&As[m][(tid & 7) * 2] = t;
        }
        // B tile: 16 kpairs x 128 n.
#pragma unroll
        for (int p = 0; p < 2; p++) {
            int kp = (tid >> 5) + 8 * p;
            int n4 = (tid & 31) * 4;
            const float* w0 = W + (size_t)(kc + 2 * kp) * 512 + n4;
            float4 v0 = *(const float4*)w0;
            float4 v1 = *(const float4*)(w0 + 512);
            uint4 t;
            t.x = packh2(v0.x, v1.x);
            t.y = packh2(v0.y, v1.y);
            t.z = packh2(v0.z, v1.z);
            t.w = packh2(v0.w, v1.w);
            *(uint4*)&Bs[kp][n4] = t;
        }
        __syncthreads();

#pragma unroll
        for (int kk = 0; kk < 2; kk++) {
            uint32_t a[2][4];
#pragma unroll
            for (int mt = 0; mt < 2; mt++) {
                int mb = warpM * 32 + mt * 16;
                int r = lane >> 2, kq = kk * 8 + (lane & 3);
                a[mt][0] = As[mb + r][kq];
                a[mt][1] = As[mb + r + 8][kq];
                a[mt][2] = As[mb + r][kq + 4];
                a[mt][3] = As[mb + r + 8][kq + 4];
            }
#pragma unroll
            for (int nt = 0; nt < 8; nt++) {
                int nb = warpN * 64 + nt * 8;
                uint32_t b[2];
                b[0] = Bs[kk * 8 + (lane & 3)][nb + (lane >> 2)];
                b[1] = Bs[kk * 8 + (lane & 3) + 4][nb + (lane >> 2)];
                mma_f16(acc[0][nt], a[0], b);
                mma_f16(acc[1][nt], a[1], b);
            }
        }
        __syncthreads();
    }

    // Partial epilogue: write fp32 partials (virtual cols 0..1023).
    float* Cout = g_S + (size_t)kz * BN * KTOT;
#pragma unroll
    for (int mt = 0; mt < 2; mt++)
#pragma unroll
        for (int nt = 0; nt < 8; nt++)
#pragma unroll
            for (int rh = 0; rh < 2; rh++)
#pragma unroll
                for (int e = 0; e < 2; e++) {
                    int row = mblk + warpM * 32 + mt * 16 + (lane >> 2) + rh * 8;
                    int col = nblk + warpN * 64 + nt * 8 + (lane & 3) * 2 + e;
                    Cout[(size_t)row * KTOT + col] = acc[mt][nt][rh * 2 + e];
                }
}

// ---------------------------------------------------------------------------
// Combine: G/H feat cols = S[0] + S[1].  1152 blocks x 256 thr x float4.
// ---------------------------------------------------------------------------
__global__ __launch_bounds__(256)
void combine() {
    const int row = blockIdx.x;
    const int c4  = threadIdx.x * 4;             // 0..1020
    const float4 a = *(const float4*)(g_S + (size_t)row * KTOT + c4);
    const float4 b = *(const float4*)(g_S + (size_t)(BN + row) * KTOT + c4);
    float4 v;
    v.x = a.x + b.x; v.y = a.y + b.y; v.z = a.z + b.z; v.w = a.w + b.w;
    if (c4 < 512)
        *(float4*)(g_G + (size_t)row * KTOT + c4) = v;
    else
        *(float4*)(g_H + (size_t)row * KTOT + (c4 - 512)) = v;
}

// ---------------------------------------------------------------------------
// Z precompute: g_Zh[pair][r] = fp16(relu(G[gi][r] * H[b*36+j][r]))
// ---------------------------------------------------------------------------
__global__ __launch_bounds__(256)
void zbuild() {
    const int gi = blockIdx.x;            // 0..1151
    const int b  = gi / 36;
    const int t  = threadIdx.x;           // 0..255, KTOT/4 = 256

    float4 g = ((const float4*)(g_G + (size_t)gi * KTOT))[t];
    const float4* Hb = (const float4*)(g_H + (size_t)b * 36 * KTOT);
    uint2* Zb = (uint2*)(g_Zh + (size_t)gi * 36 * KTOT);

#pragma unroll 4
    for (int j = 0; j < 36; j++) {
        float4 h = Hb[j * (KTOT / 4) + t];
        uint2 z;
        z.x = packh2(fmaxf(g.x * h.x, 0.f), fmaxf(g.y * h.y, 0.f));
        z.y = packh2(fmaxf(g.z * h.z, 0.f), fmaxf(g.w * h.w, 0.f));
        Zb[j * (KTOT / 4) + t] = z;
    }
}

// ---------------------------------------------------------------------------
// Main kernel: pipelined fp16 GEMM, 4 CTAs/SM, XOR-swizzled smem,
//   hoisted cp.async addressing. One barrier per chunk. (Unchanged from R10.)
// ---------------------------------------------------------------------------
#define ASZ   (DTILE * 128)          // 8192 B per A buffer
#define ZSZ   (NCOL * 128)           // 18432 B per Z buffer
#define OFF_A   0
#define OFF_Z   (2 * ASZ)            // 16384
#define SMEM_MAIN (OFF_Z + 2 * ZSZ)  // 53248

__global__ __launch_bounds__(NTHR, 4)
void pairwise_mm(const float* __restrict__ mm, float* __restrict__ out) {
    extern __shared__ char smem[];
    const uint32_t sbase = smem_u32(smem);

    const int tid = threadIdx.x;
    const int lane = tid & 31, wid = tid >> 5;
    const int warpM = wid & 1, warpN = wid >> 1;
    const int d0 = blockIdx.x * DTILE;
    const int i0 = blockIdx.y * 4;                      // 4 global i rows
    const size_t zrow0 = (size_t)blockIdx.y * NCOL;     // first pair row

    // ---- hoisted cp.async addressing ----
    const int r8 = tid >> 3;                 // 0..15
    const int kq = tid & 7;
    const uint32_t cpdst = r8 * 128 + ((kq ^ (r8 & 7)) << 4);
    const __half* srcA = g_PTh + (size_t)(d0 + r8) * KTOT + kq * 8;
    const __half* srcZ = g_Zh + (zrow0 + r8) * KTOT + kq * 8;

    // ---- issue chunk 0 (A + Z) ----
    {
#pragma unroll
        for (int q = 0; q < 4; q++)
            cp16(sbase + OFF_A + cpdst + q * 2048, srcA + (size_t)q * 16 * KTOT);
#pragma unroll
        for (int p = 0; p < 9; p++)
            cp16(sbase + OFF_Z + cpdst + p * 2048, srcZ + (size_t)p * 16 * KTOT);
        CP_COMMIT();
    }

    // ---- per-thread ldmatrix row bases (bytes) and swizzle params ----
    const int sx = lane & 7;
    const int aRow  = (warpM * 32 + (lane & 15)) * 128;
    const int kbitA = lane >> 4;
    const int bRow  = (warpN * 72 + (lane & 7) + ((lane >> 4) << 3)) * 128;
    const int kbitB = (lane >> 3) & 1;
    const int l2 = lane & 15;
    const int b2Row  = (warpN * 72 + 64 + (l2 & 7)) * 128;
    const int kbitB2 = l2 >> 3;

    float acc[2][9][4];
#pragma unroll
    for (int mt = 0; mt < 2; mt++)
#pragma unroll
        for (int nt = 0; nt < 9; nt++)
#pragma unroll
            for (int q = 0; q < 4; q++) acc[mt][nt][q] = 0.f;

    for (int c = 0; c < KTOT / KC; c++) {        // 16 chunks of 64 halves
        const int buf = c & 1;
        const uint32_t Zb = sbase + OFF_Z + buf * ZSZ;
        const uint32_t Ab = sbase + OFF_A + buf * ASZ;

        // ---- single rendezvous: chunk-c data resident, other buffer free ----
        CP_WAIT0();
        __syncthreads();

        // ---- issue chunk c+1 into the freed buffer (covers under MMA) ----
        if (c < KTOT / KC - 1) {
            const uint32_t An = sbase + OFF_A + (buf ^ 1) * ASZ;
            const uint32_t Zn = sbase + OFF_Z + (buf ^ 1) * ZSZ;
            const __half* sA = srcA + (size_t)(c + 1) * KC;
            const __half* sZ = srcZ + (size_t)(c + 1) * KC;
#pragma unroll
            for (int q = 0; q < 4; q++)
                cp16(An + cpdst + q * 2048, sA + (size_t)q * 16 * KTOT);
#pragma unroll
            for (int p = 0; p < 9; p++)
                cp16(Zn + cpdst + p * 2048, sZ + (size_t)p * 16 * KTOT);
            CP_COMMIT();
        }

        // ---- fragments + MMA: 4 k16-steps per chunk ----
#pragma unroll
        for (int kk = 0; kk < 4; kk++) {
            const int kk2 = kk * 2;
            const int swA  = (((kk2 + kbitA)  ^ sx) << 4);
            const int swB  = (((kk2 + kbitB)  ^ sx) << 4);
            const int swB2 = (((kk2 + kbitB2) ^ sx) << 4);

            uint32_t a[2][4];
#pragma unroll
            for (int mt = 0; mt < 2; mt++) {
                uint32_t addr = Ab + aRow + mt * (16 * 128) + swA;
                ldsm_x4(a[mt][0], a[mt][1], a[mt][2], a[mt][3], addr);
            }
            uint32_t b[9][2];
#pragma unroll
            for (int p = 0; p < 4; p++) {
                uint32_t addr = Zb + bRow + p * (16 * 128) + swB;
                ldsm_x4(b[p * 2][0], b[p * 2][1], b[p * 2 + 1][0], b[p * 2 + 1][1], addr);
            }
            {
                uint32_t addr = Zb + b2Row + swB2;
                ldsm_x2(b[8][0], b[8][1], addr);
            }
#pragma unroll
            for (int nt = 0; nt < 9; nt++) {
                mma_f16(acc[0][nt], a[0], b[nt]);
                mma_f16(acc[1][nt], a[1], b[nt]);
            }
        }
    }

    // ---- Epilogue: max over j within each 36-group, + residual ----
    const int s = lane & 3;
    float gmax[2][2][2];   // [mt][rowhalf][group]
#pragma unroll
    for (int mt = 0; mt < 2; mt++)
#pragma unroll
        for (int rh = 0; rh < 2; rh++)
#pragma unroll
            for (int g2 = 0; g2 < 2; g2++) gmax[mt][rh][g2] = -1e30f;

#pragma unroll
    for (int nt = 0; nt < 9; nt++) {
#pragma unroll
        for (int e = 0; e < 2; e++) {
            int nloc = nt * 8 + s * 2 + e;      // 0..71
            int g2 = (nloc >= 36) ? 1 : 0;
#pragma unroll
            for (int mt = 0; mt < 2; mt++)
#pragma unroll
                for (int rh = 0; rh < 2; rh++) {
                    float v = acc[mt][nt][rh * 2 + e];
                    gmax[mt][rh][g2] = fmaxf(gmax[mt][rh][g2], v);
                }
        }
    }
#pragma unroll
    for (int mt = 0; mt < 2; mt++)
#pragma unroll
        for (int rh = 0; rh < 2; rh++)
#pragma unroll
            for (int g2 = 0; g2 < 2; g2++) {
                float v = gmax[mt][rh][g2];
                v = fmaxf(v, __shfl_xor_sync(0xffffffffu, v, 1));
                v = fmaxf(v, __shfl_xor_sync(0xffffffffu, v, 2));
                gmax[mt][rh][g2] = v;
            }

    if (s < 2) {
        int iglob = i0 + warpN * 2 + s;
        size_t rowbase = (size_t)iglob * DIM;
#pragma unroll
        for (int mt = 0; mt < 2; mt++)
#pragma unroll
            for (int rh = 0; rh < 2; rh++) {
                int d = d0 + warpM * 32 + mt * 16 + (lane >> 2) + rh * 8;
                out[rowbase + d] = gmax[mt][rh][s] + mm[rowbase + d];
            }
    }
}

// ---------------------------------------------------------------------------
extern "C" void kernel_launch(void* const* d_in, const int* in_sizes, int n_in,
                              void* d_out, int out_size) {
    const float* mm     = (const float*)d_in[0];
    const float* coords = (const float*)d_in[1];
    const float* Uf     = (const float*)d_in[2];
    const float* Vf     = (const float*)d_in[3];
    const float* Pf     = (const float*)d_in[4];
    const float* Uc     = (const float*)d_in[5];
    const float* Vc     = (const float*)d_in[6];
    const float* Pc     = (const float*)d_in[7];
    float* out = (float*)d_out;

    cudaFuncSetAttribute(pairwise_mm,
                         cudaFuncAttributeMaxDynamicSharedMemorySize, SMEM_MAIN);

    prelude<<<4352, 256>>>(Pf, Pc, coords, Uc, Vc);        // launch 0

    dim3 g1(8, 9, 2);                                      // split-K, 144 CTAs
    stage1_feat<<<g1, 256>>>(mm, Uf, Vf);                  // launch 1

    combine<<<BN, 256>>>();                                // launch 2

    zbuild<<<BN, 256>>>();                                 // launch 3

    dim3 g2(DIM / DTILE, BN / 4);   // 32 x 288
    pairwise_mm<<<g2, NTHR, SMEM_MAIN>>>(mm, out);         // launch 4
}

// round 13
// speedup vs baseline: 1.1385x; 1.0185x over previous
#include <cuda_runtime.h>
#include <cuda_fp16.h>
#include <cstdint>
#include <cstddef>

// Problem constants
#define BATCH 32
#define NREG  36
#define DIM   2048
#define RANK  512
#define KTOT  1024              // 2*RANK (feat || coord)
#define BN    (BATCH * NREG)    // 1152
#define NPAIR (BN * NREG)       // 41472 pair rows

// Main kernel tiling (4 CTAs/SM)
#define DTILE 64                // d columns per CTA
#define NCOL  144               // 4 i x 36 j pair-columns per CTA
#define KC    64                // k (halves) per chunk = 128 B per row
#define NTHR  128

// Scratch
__device__ float g_G[BN * KTOT];
__device__ float g_H[BN * KTOT];
__device__ float g_S[2 * BN * KTOT];              // split-K partials (9.4 MB)
__device__ __half g_PTh[(size_t)DIM * KTOT];      // P^T as fp16: PT[d][r]
__device__ __half g_Zh[(size_t)NPAIR * KTOT];     // Z[pair][r] as fp16 (~85 MB)

// ---------------------------------------------------------------------------
__device__ __forceinline__ uint32_t smem_u32(const void* p) {
    uint32_t a;
    asm("{ .reg .u64 t; cvta.to.shared.u64 t, %1; cvt.u32.u64 %0, t; }" : "=r"(a) : "l"(p));
    return a;
}

// fp16 MMA: D(16x8,f32) += A(16x16,f16) * B(16x8,f16)
__device__ __forceinline__ void mma_f16(float c[4], const uint32_t a[4], const uint32_t b[2]) {
    asm volatile(
        "mma.sync.aligned.m16n8k16.row.col.f32.f16.f16.f32 "
        "{%0,%1,%2,%3}, {%4,%5,%6,%7}, {%8,%9}, {%0,%1,%2,%3};\n"
        : "+f"(c[0]), "+f"(c[1]), "+f"(c[2]), "+f"(c[3])
        : "r"(a[0]), "r"(a[1]), "r"(a[2]), "r"(a[3]), "r"(b[0]), "r"(b[1]));
}

__device__ __forceinline__ void ldsm_x4(uint32_t& r0, uint32_t& r1, uint32_t& r2, uint32_t& r3,
                                        uint32_t addr) {
    asm volatile("ldmatrix.sync.aligned.m8n8.x4.shared.b16 {%0,%1,%2,%3}, [%4];"
                 : "=r"(r0), "=r"(r1), "=r"(r2), "=r"(r3) : "r"(addr));
}
__device__ __forceinline__ void ldsm_x2(uint32_t& r0, uint32_t& r1, uint32_t addr) {
    asm volatile("ldmatrix.sync.aligned.m8n8.x2.shared.b16 {%0,%1}, [%2];"
                 : "=r"(r0), "=r"(r1) : "r"(addr));
}

__device__ __forceinline__ void cp16(uint32_t dst, const void* src) {
    asm volatile("cp.async.cg.shared.global [%0], [%1], 16;" :: "r"(dst), "l"(src) : "memory");
}
#define CP_COMMIT() asm volatile("cp.async.commit_group;" ::: "memory")
#define CP_WAIT0()  asm volatile("cp.async.wait_group 0;" ::: "memory")

__device__ __forceinline__ uint32_t packh2(float lo, float hi) {
    __half2 h = __floats2half2_rn(lo, hi);
    return *(uint32_t*)&h;
}

// ---------------------------------------------------------------------------
// prep2: fused stage1 split-K (blocks 0..143, VALIDATED 128x128 tile) +
//        transpose_P (144..2191) + coord projections (2192..4495).
//   Stage1 CTAs dispatch first (1/SM), prelude blocks backfill remaining
//   occupancy -> prelude runs ~free under stage1.
// ---------------------------------------------------------------------------
__global__ __launch_bounds__(256, 2)
void prep2(const float* __restrict__ mm,
           const float* __restrict__ Uf, const float* __restrict__ Vf,
           const float* __restrict__ Pf, const float* __restrict__ Pc,
           const float* __restrict__ coords,
           const float* __restrict__ Uc, const float* __restrict__ Vc) {
    __shared__ uint32_t As[128][20];   // stage1 A: [m][kpair]
    __shared__ uint32_t Bs[16][136];   // stage1 B: [kpair][n]
    __shared__ float    t[32][33];     // transpose tile

    const int tid = threadIdx.x;

    if (blockIdx.x >= 144) {
        int bx2 = blockIdx.x - 144;
        if (bx2 < 2048) {
            // ---- transpose P = [Pf ; Pc] -> PTh fp16 ----
            int r0 = (bx2 & 31) * 32;
            int d0 = (bx2 >> 5) * 32;
            int tx = tid & 31, ty = tid >> 5;     // 32 x 8
#pragma unroll
            for (int q = 0; q < 4; q++) {
                int r = r0 + ty + q * 8;
                const float* src = (r < RANK) ? (Pf + (size_t)r * DIM)
                                              : (Pc + (size_t)(r - RANK) * DIM);
                t[ty + q * 8][tx] = src[d0 + tx];
            }
            __syncthreads();
#pragma unroll
            for (int q = 0; q < 4; q++) {
                int d = d0 + ty + q * 8;
                g_PTh[(size_t)d * KTOT + r0 + tx] = __float2half_rn(t[tx][ty + q * 8]);
            }
        } else {
            // ---- coord projections (K=4) ----
            int idx = (bx2 - 2048) * 256 + tid;   // [0, BN*RANK)
            int row = idx >> 9;
            int n   = idx & 511;
            const float* c = coords + row * 4;
            float c0 = c[0], c1 = c[1], c2 = c[2], c3 = c[3];
            g_G[(size_t)row * KTOT + RANK + n] =
                c0 * Uc[n] + c1 * Uc[512 + n] + c2 * Uc[1024 + n] + c3 * Uc[1536 + n];
            g_H[(size_t)row * KTOT + RANK + n] =
                c0 * Vc[n] + c1 * Vc[512 + n] + c2 * Vc[1024 + n] + c3 * Vc[1536 + n];
        }
        return;
    }

    // ---- stage1 split-K: 128m x 128n tile, half of K per CTA ----
    const int lane = tid & 31, wid = tid >> 5;
    const int warpM = wid & 3, warpN = wid >> 2;
    const int kz   = blockIdx.x / 72;             // 0 or 1
    const int rem  = blockIdx.x - kz * 72;
    const int nblk = (rem & 7) * 128;
    const int mblk = (rem >> 3) * 128;
    const int kbeg = kz * (DIM / 2);
    const int kend = kbeg + (DIM / 2);

    const float* W = (nblk < 512) ? (Uf + nblk) : (Vf + (nblk - 512));

    float acc[2][8][4];
#pragma unroll
    for (int mt = 0; mt < 2; mt++)
#pragma unroll
        for (int nt = 0; nt < 8; nt++)
#pragma unroll
            for (int q = 0; q < 4; q++) acc[mt][nt][q] = 0.f;

    for (int kc = kbeg; kc < kend; kc += 32) {
#pragma unroll
        for (int p = 0; p < 4; p++) {
            int m  = (tid >> 3) + 32 * p;
            int k4 = (tid & 7) * 4;
            float4 v = *(const float4*)(mm + (size_t)(mblk + m) * DIM + kc + k4);
            uint2 tt;
            tt.x = packh2(v.x, v.y);
            tt.y = packh2(v.z, v.w);
            *(uint2*)&As[m][(tid & 7) * 2] = tt;
        }
#pragma unroll
        for (int p = 0; p < 2; p++) {
            int kp = (tid >> 5) + 8 * p;
            int n4 = (tid & 31) * 4;
            const float* w0 = W + (size_t)(kc + 2 * kp) * 512 + n4;
            float4 v0 = *(const float4*)w0;
            float4 v1 = *(const float4*)(w0 + 512);
            uint4 tt;
            tt.x = packh2(v0.x, v1.x);
            tt.y = packh2(v0.y, v1.y);
            tt.z = packh2(v0.z, v1.z);
            tt.w = packh2(v0.w, v1.w);
            *(uint4*)&Bs[kp][n4] = tt;
        }
        __syncthreads();

#pragma unroll
        for (int kk = 0; kk < 2; kk++) {
            uint32_t a[2][4];
#pragma unroll
            for (int mt = 0; mt < 2; mt++) {
                int mb = warpM * 32 + mt * 16;
                int r = lane >> 2, kq = kk * 8 + (lane & 3);
                a[mt][0] = As[mb + r][kq];
                a[mt][1] = As[mb + r + 8][kq];
                a[mt][2] = As[mb + r][kq + 4];
                a[mt][3] = As[mb + r + 8][kq + 4];
            }
#pragma unroll
            for (int nt = 0; nt < 8; nt++) {
                int nb = warpN * 64 + nt * 8;
                uint32_t b[2];
                b[0] = Bs[kk * 8 + (lane & 3)][nb + (lane >> 2)];
                b[1] = Bs[kk * 8 + (lane & 3) + 4][nb + (lane >> 2)];
                mma_f16(acc[0][nt], a[0], b);
                mma_f16(acc[1][nt], a[1], b);
            }
        }
        __syncthreads();
    }

    float* Cout = g_S + (size_t)kz * BN * KTOT;
#pragma unroll
    for (int mt = 0; mt < 2; mt++)
#pragma unroll
        for (int nt = 0; nt < 8; nt++)
#pragma unroll
            for (int rh = 0; rh < 2; rh++)
#pragma unroll
                for (int e = 0; e < 2; e++) {
                    int row = mblk + warpM * 32 + mt * 16 + (lane >> 2) + rh * 8;
                    int col = nblk + warpN * 64 + nt * 8 + (lane & 3) * 2 + e;
                    Cout[(size_t)row * KTOT + col] = acc[mt][nt][rh * 2 + e];
                }
}

// ---------------------------------------------------------------------------
// Combine: G/H feat cols = S[0] + S[1].  1152 blocks x 256 thr x float4.
// ---------------------------------------------------------------------------
__global__ __launch_bounds__(256)
void combine() {
    const int row = blockIdx.x;
    const int c4  = threadIdx.x * 4;             // 0..1020
    const float4 a = *(const float4*)(g_S + (size_t)row * KTOT + c4);
    const float4 b = *(const float4*)(g_S + (size_t)(BN + row) * KTOT + c4);
    float4 v;
    v.x = a.x + b.x; v.y = a.y + b.y; v.z = a.z + b.z; v.w = a.w + b.w;
    if (c4 < 512)
        *(float4*)(g_G + (size_t)row * KTOT + c4) = v;
    else
        *(float4*)(g_H + (size_t)row * KTOT + (c4 - 512)) = v;
}

// ---------------------------------------------------------------------------
// Z precompute (wide-store): 2 j-lanes x 128 threads; each thread owns 8
//   contiguous k -> per j: 2x LDG.128 + 1x STG.128, 18 iterations.
// ---------------------------------------------------------------------------
__global__ __launch_bounds__(256)
void zbuild() {
    const int gi = blockIdx.x;             // 0..1151
    const int b  = gi / 36;
    const int jl = threadIdx.x >> 7;       // 0..1
    const int t  = threadIdx.x & 127;      // k offset = t*8

    const float4* Gr = (const float4*)(g_G + (size_t)gi * KTOT) + t * 2;
    const float4 g0 = Gr[0], g1 = Gr[1];

    const float* Hbase = g_H + (size_t)b * 36 * KTOT + t * 8;
    __half* Zbase = g_Zh + (size_t)gi * 36 * KTOT + t * 8;

#pragma unroll 3
    for (int j2 = 0; j2 < 18; j2++) {
        const int j = j2 * 2 + jl;
        const float4* Hr = (const float4*)(Hbase + (size_t)j * KTOT);
        float4 h0 = Hr[0], h1 = Hr[1];
        uint4 z;
        z.x = packh2(fmaxf(g0.x * h0.x, 0.f), fmaxf(g0.y * h0.y, 0.f));
        z.y = packh2(fmaxf(g0.z * h0.z, 0.f), fmaxf(g0.w * h0.w, 0.f));
        z.z = packh2(fmaxf(g1.x * h1.x, 0.f), fmaxf(g1.y * h1.y, 0.f));
        z.w = packh2(fmaxf(g1.z * h1.z, 0.f), fmaxf(g1.w * h1.w, 0.f));
        *(uint4*)(Zbase + (size_t)j * KTOT) = z;
    }
}

// ---------------------------------------------------------------------------
// Main kernel: pipelined fp16 GEMM, 4 CTAs/SM, XOR-swizzled smem,
//   hoisted cp.async addressing. One barrier per chunk. (Unchanged from R12.)
// ---------------------------------------------------------------------------
#define ASZ   (DTILE * 128)          // 8192 B per A buffer
#define ZSZ   (NCOL * 128)           // 18432 B per Z buffer
#define OFF_A   0
#define OFF_Z   (2 * ASZ)            // 16384
#define SMEM_MAIN (OFF_Z + 2 * ZSZ)  // 53248

__global__ __launch_bounds__(NTHR, 4)
void pairwise_mm(const float* __restrict__ mm, float* __restrict__ out) {
    extern __shared__ char smem[];
    const uint32_t sbase = smem_u32(smem);

    const int tid = threadIdx.x;
    const int lane = tid & 31, wid = tid >> 5;
    const int warpM = wid & 1, warpN = wid >> 1;
    const int d0 = blockIdx.x * DTILE;
    const int i0 = blockIdx.y * 4;                      // 4 global i rows
    const size_t zrow0 = (size_t)blockIdx.y * NCOL;     // first pair row

    // ---- hoisted cp.async addressing ----
    const int r8 = tid >> 3;                 // 0..15
    const int kq = tid & 7;
    const uint32_t cpdst = r8 * 128 + ((kq ^ (r8 & 7)) << 4);
    const __half* srcA = g_PTh + (size_t)(d0 + r8) * KTOT + kq * 8;
    const __half* srcZ = g_Zh + (zrow0 + r8) * KTOT + kq * 8;

    // ---- issue chunk 0 (A + Z) ----
    {
#pragma unroll
        for (int q = 0; q < 4; q++)
            cp16(sbase + OFF_A + cpdst + q * 2048, srcA + (size_t)q * 16 * KTOT);
#pragma unroll
        for (int p = 0; p < 9; p++)
            cp16(sbase + OFF_Z + cpdst + p * 2048, srcZ + (size_t)p * 16 * KTOT);
        CP_COMMIT();
    }

    // ---- per-thread ldmatrix row bases (bytes) and swizzle params ----
    const int sx = lane & 7;
    const int aRow  = (warpM * 32 + (lane & 15)) * 128;
    const int kbitA = lane >> 4;
    const int bRow  = (warpN * 72 + (lane & 7) + ((lane >> 4) << 3)) * 128;
    const int kbitB = (lane >> 3) & 1;
    const int l2 = lane & 15;
    const int b2Row  = (warpN * 72 + 64 + (l2 & 7)) * 128;
    const int kbitB2 = l2 >> 3;

    float acc[2][9][4];
#pragma unroll
    for (int mt = 0; mt < 2; mt++)
#pragma unroll
        for (int nt = 0; nt < 9; nt++)
#pragma unroll
            for (int q = 0; q < 4; q++) acc[mt][nt][q] = 0.f;

    for (int c = 0; c < KTOT / KC; c++) {        // 16 chunks of 64 halves
        const int buf = c & 1;
        const uint32_t Zb = sbase + OFF_Z + buf * ZSZ;
        const uint32_t Ab = sbase + OFF_A + buf * ASZ;

        // ---- single rendezvous: chunk-c data resident, other buffer free ----
        CP_WAIT0();
        __syncthreads();

        // ---- issue chunk c+1 into the freed buffer (covers under MMA) ----
        if (c < KTOT / KC - 1) {
            const uint32_t An = sbase + OFF_A + (buf ^ 1) * ASZ;
            const uint32_t Zn = sbase + OFF_Z + (buf ^ 1) * ZSZ;
            const __half* sA = srcA + (size_t)(c + 1) * KC;
            const __half* sZ = srcZ + (size_t)(c + 1) * KC;
#pragma unroll
            for (int q = 0; q < 4; q++)
                cp16(An + cpdst + q * 2048, sA + (size_t)q * 16 * KTOT);
#pragma unroll
            for (int p = 0; p < 9; p++)
                cp16(Zn + cpdst + p * 2048, sZ + (size_t)p * 16 * KTOT);
            CP_COMMIT();
        }

        // ---- fragments + MMA: 4 k16-steps per chunk ----
#pragma unroll
        for (int kk = 0; kk < 4; kk++) {
            const int kk2 = kk * 2;
            const int swA  = (((kk2 + kbitA)  ^ sx) << 4);
            const int swB  = (((kk2 + kbitB)  ^ sx) << 4);
            const int swB2 = (((kk2 + kbitB2) ^ sx) << 4);

            uint32_t a[2][4];
#pragma unroll
            for (int mt = 0; mt < 2; mt++) {
                uint32_t addr = Ab + aRow + mt * (16 * 128) + swA;
                ldsm_x4(a[mt][0], a[mt][1], a[mt][2], a[mt][3], addr);
            }
            uint32_t b[9][2];
#pragma unroll
            for (int p = 0; p < 4; p++) {
                uint32_t addr = Zb + bRow + p * (16 * 128) + swB;
                ldsm_x4(b[p * 2][0], b[p * 2][1], b[p * 2 + 1][0], b[p * 2 + 1][1], addr);
            }
            {
                uint32_t addr = Zb + b2Row + swB2;
                ldsm_x2(b[8][0], b[8][1], addr);
            }
#pragma unroll
            for (int nt = 0; nt < 9; nt++) {
                mma_f16(acc[0][nt], a[0], b[nt]);
                mma_f16(acc[1][nt], a[1], b[nt]);
            }
        }
    }

    // ---- Epilogue: max over j within each 36-group, + residual ----
    const int s = lane & 3;
    float gmax[2][2][2];   // [mt][rowhalf][group]
#pragma unroll
    for (int mt = 0; mt < 2; mt++)
#pragma unroll
        for (int rh = 0; rh < 2; rh++)
#pragma unroll
            for (int g2 = 0; g2 < 2; g2++) gmax[mt][rh][g2] = -1e30f;

#pragma unroll
    for (int nt = 0; nt < 9; nt++) {
#pragma unroll
        for (int e = 0; e < 2; e++) {
            int nloc = nt * 8 + s * 2 + e;      // 0..71
            int g2 = (nloc >= 36) ? 1 : 0;
#pragma unroll
            for (int mt = 0; mt < 2; mt++)
#pragma unroll
                for (int rh = 0; rh < 2; rh++) {
                    float v = acc[mt][nt][rh * 2 + e];
                    gmax[mt][rh][g2] = fmaxf(gmax[mt][rh][g2], v);
                }
        }
    }
#pragma unroll
    for (int mt = 0; mt < 2; mt++)
#pragma unroll
        for (int rh = 0; rh < 2; rh++)
#pragma unroll
            for (int g2 = 0; g2 < 2; g2++) {
                float v = gmax[mt][rh][g2];
                v = fmaxf(v, __shfl_xor_sync(0xffffffffu, v, 1));
                v = fmaxf(v, __shfl_xor_sync(0xffffffffu, v, 2));
                gmax[mt][rh][g2] = v;
            }

    if (s < 2) {
        int iglob = i0 + warpN * 2 + s;
        size_t rowbase = (size_t)iglob * DIM;
#pragma unroll
        for (int mt = 0; mt < 2; mt++)
#pragma unroll
            for (int rh = 0; rh < 2; rh++) {
                int d = d0 + warpM * 32 + mt * 16 + (lane >> 2) + rh * 8;
                out[rowbase + d] = gmax[mt][rh][s] + mm[rowbase + d];
            }
    }
}

// ---------------------------------------------------------------------------
extern "C" void kernel_launch(void* const* d_in, const int* in_sizes, int n_in,
                              void* d_out, int out_size) {
    const float* mm     = (const float*)d_in[0];
    const float* coords = (const float*)d_in[1];
    const float* Uf     = (const float*)d_in[2];
    const float* Vf     = (const float*)d_in[3];
    const float* Pf     = (const float*)d_in[4];
    const float* Uc     = (const float*)d_in[5];
    const float* Vc     = (const float*)d_in[6];
    const float* Pc     = (const float*)d_in[7];
    float* out = (float*)d_out;

    cudaFuncSetAttribute(pairwise_mm,
                         cudaFuncAttributeMaxDynamicSharedMemorySize, SMEM_MAIN);

    prep2<<<4496, 256>>>(mm, Uf, Vf, Pf, Pc, coords, Uc, Vc);  // launch 0

    combine<<<BN, 256>>>();                                    // launch 1

    zbuild<<<BN, 256>>>();                                     // launch 2

    dim3 g2(DIM / DTILE, BN / 4);   // 32 x 288
    pairwise_mm<<<g2, NTHR, SMEM_MAIN>>>(mm, out);             // launch 3
}

// round 14
// speedup vs baseline: 1.1618x; 1.0204x over previous
#include <cuda_runtime.h>
#include <cuda_fp16.h>
#include <cstdint>
#include <cstddef>

// Problem constants
#define BATCH 32
#define NREG  36
#define DIM   2048
#define RANK  512
#define KTOT  1024              // 2*RANK (feat || coord)
#define BN    (BATCH * NREG)    // 1152
#define NPAIR (BN * NREG)       // 41472 pair rows

// Main kernel tiling (4 CTAs/SM)
#define DTILE 64                // d columns per CTA
#define NCOL  144               // 4 i x 36 j pair-columns per CTA
#define KC    64                // k (halves) per chunk = 128 B per row
#define NTHR  128

// Split-K depth for stage1
#define SPLITK 4

// Scratch
__device__ float g_G[BN * KTOT];
__device__ float g_H[BN * KTOT];
__device__ float g_S[SPLITK * BN * KTOT];         // split-K partials (18.9 MB)
__device__ __half g_PTh[(size_t)DIM * KTOT];      // P^T as fp16: PT[d][r]
__device__ __half g_Zh[(size_t)NPAIR * KTOT];     // Z[pair][r] as fp16 (~85 MB)

// ---------------------------------------------------------------------------
__device__ __forceinline__ uint32_t smem_u32(const void* p) {
    uint32_t a;
    asm("{ .reg .u64 t; cvta.to.shared.u64 t, %1; cvt.u32.u64 %0, t; }" : "=r"(a) : "l"(p));
    return a;
}

// fp16 MMA: D(16x8,f32) += A(16x16,f16) * B(16x8,f16)
__device__ __forceinline__ void mma_f16(float c[4], const uint32_t a[4], const uint32_t b[2]) {
    asm volatile(
        "mma.sync.aligned.m16n8k16.row.col.f32.f16.f16.f32 "
        "{%0,%1,%2,%3}, {%4,%5,%6,%7}, {%8,%9}, {%0,%1,%2,%3};\n"
        : "+f"(c[0]), "+f"(c[1]), "+f"(c[2]), "+f"(c[3])
        : "r"(a[0]), "r"(a[1]), "r"(a[2]), "r"(a[3]), "r"(b[0]), "r"(b[1]));
}

__device__ __forceinline__ void ldsm_x4(uint32_t& r0, uint32_t& r1, uint32_t& r2, uint32_t& r3,
                                        uint32_t addr) {
    asm volatile("ldmatrix.sync.aligned.m8n8.x4.shared.b16 {%0,%1,%2,%3}, [%4];"
                 : "=r"(r0), "=r"(r1), "=r"(r2), "=r"(r3) : "r"(addr));
}
__device__ __forceinline__ void ldsm_x2(uint32_t& r0, uint32_t& r1, uint32_t addr) {
    asm volatile("ldmatrix.sync.aligned.m8n8.x2.shared.b16 {%0,%1}, [%2];"
                 : "=r"(r0), "=r"(r1) : "r"(addr));
}

__device__ __forceinline__ void cp16(uint32_t dst, const void* src) {
    asm volatile("cp.async.cg.shared.global [%0], [%1], 16;" :: "r"(dst), "l"(src) : "memory");
}
#define CP_COMMIT() asm volatile("cp.async.commit_group;" ::: "memory")
#define CP_WAIT0()  asm volatile("cp.async.wait_group 0;" ::: "memory")

__device__ __forceinline__ uint32_t packh2(float lo, float hi) {
    __half2 h = __floats2half2_rn(lo, hi);
    return *(uint32_t*)&h;
}

// ---------------------------------------------------------------------------
// prep2: fused stage1 split-K x4 (blocks 0..287, validated 128x128 tile) +
//        transpose_P (288..2335) + coord projections (2336..4639).
//   288 stage1 CTAs ~= 2/SM (occupancy 2) -> whole stage1 is ONE wave of
//   K=512 depth; prelude blocks backfill remaining slots.
// ---------------------------------------------------------------------------
__global__ __launch_bounds__(256, 2)
void prep2(const float* __restrict__ mm,
           const float* __restrict__ Uf, const float* __restrict__ Vf,
           const float* __restrict__ Pf, const float* __restrict__ Pc,
           const float* __restrict__ coords,
           const float* __restrict__ Uc, const float* __restrict__ Vc) {
    __shared__ uint32_t As[128][20];   // stage1 A: [m][kpair]
    __shared__ uint32_t Bs[16][136];   // stage1 B: [kpair][n]
    __shared__ float    t[32][33];     // transpose tile

    const int tid = threadIdx.x;
    const int NS1 = 72 * SPLITK;       // 288 stage1 blocks

    if (blockIdx.x >= NS1) {
        int bx2 = blockIdx.x - NS1;
        if (bx2 < 2048) {
            // ---- transpose P = [Pf ; Pc] -> PTh fp16 ----
            int r0 = (bx2 & 31) * 32;
            int d0 = (bx2 >> 5) * 32;
            int tx = tid & 31, ty = tid >> 5;     // 32 x 8
#pragma unroll
            for (int q = 0; q < 4; q++) {
                int r = r0 + ty + q * 8;
                const float* src = (r < RANK) ? (Pf + (size_t)r * DIM)
                                              : (Pc + (size_t)(r - RANK) * DIM);
                t[ty + q * 8][tx] = src[d0 + tx];
            }
            __syncthreads();
#pragma unroll
            for (int q = 0; q < 4; q++) {
                int d = d0 + ty + q * 8;
                g_PTh[(size_t)d * KTOT + r0 + tx] = __float2half_rn(t[tx][ty + q * 8]);
            }
        } else {
            // ---- coord projections (K=4) ----
            int idx = (bx2 - 2048) * 256 + tid;   // [0, BN*RANK)
            int row = idx >> 9;
            int n   = idx & 511;
            const float* c = coords + row * 4;
            float c0 = c[0], c1 = c[1], c2 = c[2], c3 = c[3];
            g_G[(size_t)row * KTOT + RANK + n] =
                c0 * Uc[n] + c1 * Uc[512 + n] + c2 * Uc[1024 + n] + c3 * Uc[1536 + n];
            g_H[(size_t)row * KTOT + RANK + n] =
                c0 * Vc[n] + c1 * Vc[512 + n] + c2 * Vc[1024 + n] + c3 * Vc[1536 + n];
        }
        return;
    }

    // ---- stage1 split-K x4: 128m x 128n tile, quarter of K per CTA ----
    const int lane = tid & 31, wid = tid >> 5;
    const int warpM = wid & 3, warpN = wid >> 2;
    const int kz   = blockIdx.x / 72;             // 0..3
    const int rem  = blockIdx.x - kz * 72;
    const int nblk = (rem & 7) * 128;
    const int mblk = (rem >> 3) * 128;
    const int kbeg = kz * (DIM / SPLITK);
    const int kend = kbeg + (DIM / SPLITK);

    const float* W = (nblk < 512) ? (Uf + nblk) : (Vf + (nblk - 512));

    float acc[2][8][4];
#pragma unroll
    for (int mt = 0; mt < 2; mt++)
#pragma unroll
        for (int nt = 0; nt < 8; nt++)
#pragma unroll
            for (int q = 0; q < 4; q++) acc[mt][nt][q] = 0.f;

    for (int kc = kbeg; kc < kend; kc += 32) {
#pragma unroll
        for (int p = 0; p < 4; p++) {
            int m  = (tid >> 3) + 32 * p;
            int k4 = (tid & 7) * 4;
            float4 v = *(const float4*)(mm + (size_t)(mblk + m) * DIM + kc + k4);
            uint2 tt;
            tt.x = packh2(v.x, v.y);
            tt.y = packh2(v.z, v.w);
            *(uint2*)&As[m][(tid & 7) * 2] = tt;
        }
#pragma unroll
        for (int p = 0; p < 2; p++) {
            int kp = (tid >> 5) + 8 * p;
            int n4 = (tid & 31) * 4;
            const float* w0 = W + (size_t)(kc + 2 * kp) * 512 + n4;
            float4 v0 = *(const float4*)w0;
            float4 v1 = *(const float4*)(w0 + 512);
            uint4 tt;
            tt.x = packh2(v0.x, v1.x);
            tt.y = packh2(v0.y, v1.y);
            tt.z = packh2(v0.z, v1.z);
            tt.w = packh2(v0.w, v1.w);
            *(uint4*)&Bs[kp][n4] = tt;
        }
        __syncthreads();

#pragma unroll
        for (int kk = 0; kk < 2; kk++) {
            uint32_t a[2][4];
#pragma unroll
            for (int mt = 0; mt < 2; mt++) {
                int mb = warpM * 32 + mt * 16;
                int r = lane >> 2, kq = kk * 8 + (lane & 3);
                a[mt][0] = As[mb + r][kq];
                a[mt][1] = As[mb + r + 8][kq];
                a[mt][2] = As[mb + r][kq + 4];
                a[mt][3] = As[mb + r + 8][kq + 4];
            }
#pragma unroll
            for (int nt = 0; nt < 8; nt++) {
                int nb = warpN * 64 + nt * 8;
                uint32_t b[2];
                b[0] = Bs[kk * 8 + (lane & 3)][nb + (lane >> 2)];
                b[1] = Bs[kk * 8 + (lane & 3) + 4][nb + (lane >> 2)];
                mma_f16(acc[0][nt], a[0], b);
                mma_f16(acc[1][nt], a[1], b);
            }
        }
        __syncthreads();
    }

    float* Cout = g_S + (size_t)kz * BN * KTOT;
#pragma unroll
    for (int mt = 0; mt < 2; mt++)
#pragma unroll
        for (int nt = 0; nt < 8; nt++)
#pragma unroll
            for (int rh = 0; rh < 2; rh++)
#pragma unroll
                for (int e = 0; e < 2; e++) {
                    int row = mblk + warpM * 32 + mt * 16 + (lane >> 2) + rh * 8;
                    int col = nblk + warpN * 64 + nt * 8 + (lane & 3) * 2 + e;
                    Cout[(size_t)row * KTOT + col] = acc[mt][nt][rh * 2 + e];
                }
}

// ---------------------------------------------------------------------------
// Combine: G/H feat cols = sum of SPLITK partials (fixed order, deterministic).
// ---------------------------------------------------------------------------
__global__ __launch_bounds__(256)
void combine() {
    const int row = blockIdx.x;
    const int c4  = threadIdx.x * 4;             // 0..1020
    float4 v = *(const float4*)(g_S + (size_t)row * KTOT + c4);
#pragma unroll
    for (int q = 1; q < SPLITK; q++) {
        const float4 b = *(const float4*)(g_S + (size_t)(q * BN + row) * KTOT + c4);
        v.x += b.x; v.y += b.y; v.z += b.z; v.w += b.w;
    }
    if (c4 < 512)
        *(float4*)(g_G + (size_t)row * KTOT + c4) = v;
    else
        *(float4*)(g_H + (size_t)row * KTOT + (c4 - 512)) = v;
}

// ---------------------------------------------------------------------------
// Z precompute (wide-store): 2 j-lanes x 128 threads; each thread owns 8
//   contiguous k -> per j: 2x LDG.128 + 1x STG.128, 18 iterations.
// ---------------------------------------------------------------------------
__global__ __launch_bounds__(256)
void zbuild() {
    const int gi = blockIdx.x;             // 0..1151
    const int b  = gi / 36;
    const int jl = threadIdx.x >> 7;       // 0..1
    const int t  = threadIdx.x & 127;      // k offset = t*8

    const float4* Gr = (const float4*)(g_G + (size_t)gi * KTOT) + t * 2;
    const float4 g0 = Gr[0], g1 = Gr[1];

    const float* Hbase = g_H + (size_t)b * 36 * KTOT + t * 8;
    __half* Zbase = g_Zh + (size_t)gi * 36 * KTOT + t * 8;

#pragma unroll 3
    for (int j2 = 0; j2 < 18; j2++) {
        const int j = j2 * 2 + jl;
        const float4* Hr = (const float4*)(Hbase + (size_t)j * KTOT);
        float4 h0 = Hr[0], h1 = Hr[1];
        uint4 z;
        z.x = packh2(fmaxf(g0.x * h0.x, 0.f), fmaxf(g0.y * h0.y, 0.f));
        z.y = packh2(fmaxf(g0.z * h0.z, 0.f), fmaxf(g0.w * h0.w, 0.f));
        z.z = packh2(fmaxf(g1.x * h1.x, 0.f), fmaxf(g1.y * h1.y, 0.f));
        z.w = packh2(fmaxf(g1.z * h1.z, 0.f), fmaxf(g1.w * h1.w, 0.f));
        *(uint4*)(Zbase + (size_t)j * KTOT) = z;
    }
}

// ---------------------------------------------------------------------------
// Main kernel: pipelined fp16 GEMM, 4 CTAs/SM, XOR-swizzled smem,
//   hoisted cp.async addressing. One barrier per chunk. (Unchanged from R13.)
// ---------------------------------------------------------------------------
#define ASZ   (DTILE * 128)          // 8192 B per A buffer
#define ZSZ   (NCOL * 128)           // 18432 B per Z buffer
#define OFF_A   0
#define OFF_Z   (2 * ASZ)            // 16384
#define SMEM_MAIN (OFF_Z + 2 * ZSZ)  // 53248

__global__ __launch_bounds__(NTHR, 4)
void pairwise_mm(const float* __restrict__ mm, float* __restrict__ out) {
    extern __shared__ char smem[];
    const uint32_t sbase = smem_u32(smem);

    const int tid = threadIdx.x;
    const int lane = tid & 31, wid = tid >> 5;
    const int warpM = wid & 1, warpN = wid >> 1;
    const int d0 = blockIdx.x * DTILE;
    const int i0 = blockIdx.y * 4;                      // 4 global i rows
    const size_t zrow0 = (size_t)blockIdx.y * NCOL;     // first pair row

    // ---- hoisted cp.async addressing ----
    const int r8 = tid >> 3;                 // 0..15
    const int kq = tid & 7;
    const uint32_t cpdst = r8 * 128 + ((kq ^ (r8 & 7)) << 4);
    const __half* srcA = g_PTh + (size_t)(d0 + r8) * KTOT + kq * 8;
    const __half* srcZ = g_Zh + (zrow0 + r8) * KTOT + kq * 8;

    // ---- issue chunk 0 (A + Z) ----
    {
#pragma unroll
        for (int q = 0; q < 4; q++)
            cp16(sbase + OFF_A + cpdst + q * 2048, srcA + (size_t)q * 16 * KTOT);
#pragma unroll
        for (int p = 0; p < 9; p++)
            cp16(sbase + OFF_Z + cpdst + p * 2048, srcZ + (size_t)p * 16 * KTOT);
        CP_COMMIT();
    }

    // ---- per-thread ldmatrix row bases (bytes) and swizzle params ----
    const int sx = lane & 7;
    const int aRow  = (warpM * 32 + (lane & 15)) * 128;
    const int kbitA = lane >> 4;
    const int bRow  = (warpN * 72 + (lane & 7) + ((lane >> 4) << 3)) * 128;
    const int kbitB = (lane >> 3) & 1;
    const int l2 = lane & 15;
    const int b2Row  = (warpN * 72 + 64 + (l2 & 7)) * 128;
    const int kbitB2 = l2 >> 3;

    float acc[2][9][4];
#pragma unroll
    for (int mt = 0; mt < 2; mt++)
#pragma unroll
        for (int nt = 0; nt < 9; nt++)
#pragma unroll
            for (int q = 0; q < 4; q++) acc[mt][nt][q] = 0.f;

    for (int c = 0; c < KTOT / KC; c++) {        // 16 chunks of 64 halves
        const int buf = c & 1;
        const uint32_t Zb = sbase + OFF_Z + buf * ZSZ;
        const uint32_t Ab = sbase + OFF_A + buf * ASZ;

        // ---- single rendezvous: chunk-c data resident, other buffer free ----
        CP_WAIT0();
        __syncthreads();

        // ---- issue chunk c+1 into the freed buffer (covers under MMA) ----
        if (c < KTOT / KC - 1) {
            const uint32_t An = sbase + OFF_A + (buf ^ 1) * ASZ;
            const uint32_t Zn = sbase + OFF_Z + (buf ^ 1) * ZSZ;
            const __half* sA = srcA + (size_t)(c + 1) * KC;
            const __half* sZ = srcZ + (size_t)(c + 1) * KC;
#pragma unroll
            for (int q = 0; q < 4; q++)
                cp16(An + cpdst + q * 2048, sA + (size_t)q * 16 * KTOT);
#pragma unroll
            for (int p = 0; p < 9; p++)
                cp16(Zn + cpdst + p * 2048, sZ + (size_t)p * 16 * KTOT);
            CP_COMMIT();
        }

        // ---- fragments + MMA: 4 k16-steps per chunk ----
#pragma unroll
        for (int kk = 0; kk < 4; kk++) {
            const int kk2 = kk * 2;
            const int swA  = (((kk2 + kbitA)  ^ sx) << 4);
            const int swB  = (((kk2 + kbitB)  ^ sx) << 4);
            const int swB2 = (((kk2 + kbitB2) ^ sx) << 4);

            uint32_t a[2][4];
#pragma unroll
            for (int mt = 0; mt < 2; mt++) {
                uint32_t addr = Ab + aRow + mt * (16 * 128) + swA;
                ldsm_x4(a[mt][0], a[mt][1], a[mt][2], a[mt][3], addr);
            }
            uint32_t b[9][2];
#pragma unroll
            for (int p = 0; p < 4; p++) {
                uint32_t addr = Zb + bRow + p * (16 * 128) + swB;
                ldsm_x4(b[p * 2][0], b[p * 2][1], b[p * 2 + 1][0], b[p * 2 + 1][1], addr);
            }
            {
                uint32_t addr = Zb + b2Row + swB2;
                ldsm_x2(b[8][0], b[8][1], addr);
            }
#pragma unroll
            for (int nt = 0; nt < 9; nt++) {
                mma_f16(acc[0][nt], a[0], b[nt]);
                mma_f16(acc[1][nt], a[1], b[nt]);
            }
        }
    }

    // ---- Epilogue: max over j within each 36-group, + residual ----
    const int s = lane & 3;
    float gmax[2][2][2];   // [mt][rowhalf][group]
#pragma unroll
    for (int mt = 0; mt < 2; mt++)
#pragma unroll
        for (int rh = 0; rh < 2; rh++)
#pragma unroll
            for (int g2 = 0; g2 < 2; g2++) gmax[mt][rh][g2] = -1e30f;

#pragma unroll
    for (int nt = 0; nt < 9; nt++) {
#pragma unroll
        for (int e = 0; e < 2; e++) {
            int nloc = nt * 8 + s * 2 + e;      // 0..71
            int g2 = (nloc >= 36) ? 1 : 0;
#pragma unroll
            for (int mt = 0; mt < 2; mt++)
#pragma unroll
                for (int rh = 0; rh < 2; rh++) {
                    float v = acc[mt][nt][rh * 2 + e];
                    gmax[mt][rh][g2] = fmaxf(gmax[mt][rh][g2], v);
                }
        }
    }
#pragma unroll
    for (int mt = 0; mt < 2; mt++)
#pragma unroll
        for (int rh = 0; rh < 2; rh++)
#pragma unroll
            for (int g2 = 0; g2 < 2; g2++) {
                float v = gmax[mt][rh][g2];
                v = fmaxf(v, __shfl_xor_sync(0xffffffffu, v, 1));
                v = fmaxf(v, __shfl_xor_sync(0xffffffffu, v, 2));
                gmax[mt][rh][g2] = v;
            }

    if (s < 2) {
        int iglob = i0 + warpN * 2 + s;
        size_t rowbase = (size_t)iglob * DIM;
#pragma unroll
        for (int mt = 0; mt < 2; mt++)
#pragma unroll
            for (int rh = 0; rh < 2; rh++) {
                int d = d0 + warpM * 32 + mt * 16 + (lane >> 2) + rh * 8;
                out[rowbase + d] = gmax[mt][rh][s] + mm[rowbase + d];
            }
    }
}

// ---------------------------------------------------------------------------
extern "C" void kernel_launch(void* const* d_in, const int* in_sizes, int n_in,
                              void* d_out, int out_size) {
    const float* mm     = (const float*)d_in[0];
    const float* coords = (const float*)d_in[1];
    const float* Uf     = (const float*)d_in[2];
    const float* Vf     = (const float*)d_in[3];
    const float* Pf     = (const float*)d_in[4];
    const float* Uc     = (const float*)d_in[5];
    const float* Vc     = (const float*)d_in[6];
    const float* Pc     = (const float*)d_in[7];
    float* out = (float*)d_out;

    cudaFuncSetAttribute(pairwise_mm,
                         cudaFuncAttributeMaxDynamicSharedMemorySize, SMEM_MAIN);

    prep2<<<72 * SPLITK + 4352, 256>>>(mm, Uf, Vf, Pf, Pc, coords, Uc, Vc);  // launch 0

    combine<<<BN, 256>>>();                                    // launch 1

    zbuild<<<BN, 256>>>();                                     // launch 2

    dim3 g2(DIM / DTILE, BN / 4);   // 32 x 288
    pairwise_mm<<<g2, NTHR, SMEM_MAIN>>>(mm, out);             // launch 3
}